// round 15
// baseline (speedup 1.0000x reference)
#include <cuda_runtime.h>
#include <cuda_fp16.h>
#include <cstdint>
#include <cstddef>

#define FD 128
#define NN 25000
#define NE 400000
#define TILE 128
// k_edge smem: A 34816 + B 34816 + meta (seid/ssrc/sdst/q = 4*128*4)
#define SMEM_E (69632 + 2048)
#define SMEM_N 69632
#define NODE_TILES 196 /* ceil(25000/128) */

// ---------------- device scratch (no allocation allowed) --------------------
__device__ __half g_P[NN * FD];
__device__ __half g_Q[NN * FD];
__device__ float g_eps[NN];
__device__ uint4 g_pk[NE];          // CSR order: (eid, src, dst->a_bits, 0)
__device__ __half g_W[4][FD * FD];  // [Wt,Wm,Wb,We1] stored [n*FD+k]
__device__ int g_deg[NN];           // invariant: zero on entry (restored by k_scan)
__device__ int g_off[NN];
__device__ int g_end[NN];
__device__ int g_cur[NN];
__device__ int g_arr[NN];           // arrival counters; zeroed by k_scan each launch
__device__ int g_cursor;            // invariant: zero on entry (restored by k_edge)

// ---------------- helpers ----------------------------------------------------
__device__ __forceinline__ uint32_t smem_u32(const void* p) {
    uint32_t a;
    asm("{ .reg .u64 t; cvta.to.shared.u64 t, %1; cvt.u32.u64 %0, t; }" : "=r"(a) : "l"(p));
    return a;
}
__device__ __forceinline__ void ldsm4(uint32_t r[4], uint32_t addr) {
    asm volatile("ldmatrix.sync.aligned.m8n8.x4.shared.b16 {%0,%1,%2,%3}, [%4];"
                 : "=r"(r[0]), "=r"(r[1]), "=r"(r[2]), "=r"(r[3])
                 : "r"(addr));
}
__device__ __forceinline__ void mma16816(float c[4], const uint32_t a[4], uint32_t b0,
                                         uint32_t b1) {
    asm volatile(
        "mma.sync.aligned.m16n8k16.row.col.f32.f16.f16.f32 "
        "{%0,%1,%2,%3},{%4,%5,%6,%7},{%8,%9},{%0,%1,%2,%3};"
        : "+f"(c[0]), "+f"(c[1]), "+f"(c[2]), "+f"(c[3])
        : "r"(a[0]), "r"(a[1]), "r"(a[2]), "r"(a[3]), "r"(b0), "r"(b1));
}
__device__ __forceinline__ uint32_t pack_h2(float x, float y) {
    __half2 h = __floats2half2_rn(x, y);
    return *reinterpret_cast<uint32_t*>(&h);
}
__device__ __forceinline__ float2 h2f2(uint32_t u) {
    return __half22float2(*reinterpret_cast<__half2*>(&u));
}
__device__ __forceinline__ void cp_async16(uint32_t smem_addr, const void* gptr) {
    asm volatile("cp.async.cg.shared.global [%0], [%1], 16;" ::"r"(smem_addr), "l"(gptr)
                 : "memory");
}
__device__ __forceinline__ void cp_async_wait_all() {
    asm volatile("cp.async.commit_group;\ncp.async.wait_group 0;" ::: "memory");
}

// ---------------- weight convert (stream 0) ---------------------------------
__global__ void k_wconv(const float* __restrict__ Wa1, const float* __restrict__ We1) {
    int tid = blockIdx.x * blockDim.x + threadIdx.x;
    if (tid < 4 * FD * FD) {
        int m = tid >> 14;
        int r = tid & (FD * FD - 1);
        int n = r >> 7;
        int k = r & 127;
        float w = (m < 3) ? Wa1[(m * FD + k) * FD + n] : We1[k * FD + n];
        g_W[m][n * FD + k] = __float2half(w);
    }
}

// ---------------- degree histogram (stream 1) --------------------------------
__global__ void k_hist(const int* __restrict__ dst) {
    int tid = blockIdx.x * blockDim.x + threadIdx.x;
    if (tid < NE) atomicAdd(&g_deg[dst[tid]], 1);
}

// ---------------- parallel range assignment + invariant restore -------------
__global__ void k_scan_fast(const float* __restrict__ nf, float* __restrict__ out) {
    __shared__ int wsum[8];
    __shared__ int sbase;
    int n = blockIdx.x * 256 + threadIdx.x;
    int lane = threadIdx.x & 31, w = threadIdx.x >> 5;
    int v = (n < NN) ? g_deg[n] : 0;
    if (n < NN) {
        g_deg[n] = 0;  // restore invariant for next replay's k_hist
        g_arr[n] = 0;  // arrival counters for this launch's k_edge
    }
    int x = v;
#pragma unroll
    for (int d = 1; d < 32; d <<= 1) {
        int t = __shfl_up_sync(0xffffffffu, x, d);
        if (lane >= d) x += t;
    }
    if (lane == 31) wsum[w] = x;
    __syncthreads();
    if (threadIdx.x == 0) {
        int run = 0;
#pragma unroll
        for (int i = 0; i < 8; i++) {
            int t = wsum[i];
            wsum[i] = run;
            run += t;
        }
        sbase = atomicAdd(&g_cursor, run);
    }
    __syncthreads();
    int off = sbase + wsum[w] + x - v;
    if (n < NN) {
        g_off[n] = off;
        g_cur[n] = off;
        g_end[n] = off + v;
        if (v == 0) {  // isolated node: out = nf (hv term is 0)
            const float4* s4 = reinterpret_cast<const float4*>(nf) + (size_t)n * 32;
            float4* o4 = reinterpret_cast<float4*>(out) + (size_t)n * 32;
            for (int d = 0; d < 32; d++) o4[d] = s4[d];
        }
    }
}

// ---------------- scatter: CSR records (eid, src, dst) -----------------------
__global__ void k_scatter(const int* __restrict__ dst, const int* __restrict__ src) {
    int e = blockIdx.x * blockDim.x + threadIdx.x;
    if (e < NE) {
        int p = atomicAdd(&g_cur[dst[e]], 1);
        uint4 rec;
        rec.x = (uint32_t)e;
        rec.y = (uint32_t)src[e];
        rec.z = (uint32_t)dst[e];
        rec.w = 0u;
        g_pk[p] = rec;
    }
}

// ---------------- GEMM building blocks (256 threads, C tile 128x128) --------
// A-fill gathers gh rows by CSR-ordered edge id (seid in smem)
__device__ __forceinline__ void load_A_gather(const float* __restrict__ gh,
                                              const int* __restrict__ seid, char* smem) {
    int t = threadIdx.x;
#pragma unroll
    for (int it = 0; it < 16; it++) {
        int linear = it * 256 + t;
        int r = linear >> 5;
        int c = (linear & 31) * 4;
        float4 v = __ldcg(reinterpret_cast<const float4*>(gh + (size_t)seid[r] * FD + c));
        uint2 pk;
        pk.x = pack_h2(v.x, v.y);
        pk.y = pack_h2(v.z, v.w);
        *reinterpret_cast<uint2*>(smem + r * 272 + c * 2) = pk;
    }
}
__device__ __forceinline__ void load_A(const float* __restrict__ src, int row0, int maxrow,
                                       char* smem) {
    int t = threadIdx.x;
#pragma unroll
    for (int it = 0; it < 16; it++) {
        int linear = it * 256 + t;
        int r = linear >> 5;
        int c = (linear & 31) * 4;
        float4 v = make_float4(0.f, 0.f, 0.f, 0.f);
        if (row0 + r < maxrow)
            v = __ldcg(reinterpret_cast<const float4*>(src + (size_t)(row0 + r) * FD + c));
        uint2 pk;
        pk.x = pack_h2(v.x, v.y);
        pk.y = pack_h2(v.z, v.w);
        *reinterpret_cast<uint2*>(smem + r * 272 + c * 2) = pk;
    }
}
__device__ __forceinline__ void load_B_async(const __half* __restrict__ w, char* smem) {
    int t = threadIdx.x;
    uint32_t sB = smem_u32(smem) + 34816;
#pragma unroll
    for (int it = 0; it < 8; it++) {
        int chunk = it * 256 + t;
        int n = chunk >> 4;
        int k16 = chunk & 15;
        cp_async16(sB + n * 272 + k16 * 16, w + n * FD + k16 * 8);
    }
}

// warp grid 4(M) x 2(N); warp tile 32x64; per-thread C[2][8][4]
__device__ __forceinline__ void mainloop(char* smem, float C[2][8][4]) {
    int lane = threadIdx.x & 31;
    int wid = threadIdx.x >> 5;
    int wm = wid >> 1, wn = wid & 1;
    uint32_t sA = smem_u32(smem);
    uint32_t sB = sA + 34816;
    uint32_t aA0 = sA + (wm * 32 + (lane & 15)) * 272 + (lane >> 4) * 16;
    uint32_t aA1 = aA0 + 16 * 272;
    uint32_t aB[4];
#pragma unroll
    for (int p = 0; p < 4; p++)
        aB[p] = sB + (wn * 64 + p * 16 + (lane & 7) + ((lane >> 4) & 1) * 8) * 272 +
                ((lane >> 3) & 1) * 16;
#pragma unroll
    for (int ks = 0; ks < 8; ks++) {
        uint32_t A0[4], A1[4], Bf[4][4];
        ldsm4(A0, aA0 + ks * 32);
        ldsm4(A1, aA1 + ks * 32);
#pragma unroll
        for (int p = 0; p < 4; p++) ldsm4(Bf[p], aB[p] + ks * 32);
#pragma unroll
        for (int p = 0; p < 4; p++) {
            mma16816(C[0][2 * p], A0, Bf[p][0], Bf[p][1]);
            mma16816(C[1][2 * p], A1, Bf[p][0], Bf[p][1]);
            mma16816(C[0][2 * p + 1], A0, Bf[p][2], Bf[p][3]);
            mma16816(C[1][2 * p + 1], A1, Bf[p][2], Bf[p][3]);
        }
    }
}

__device__ __forceinline__ void zero_C(float C[2][8][4]) {
#pragma unroll
    for (int a = 0; a < 2; a++)
#pragma unroll
        for (int b = 0; b < 8; b++)
#pragma unroll
            for (int c = 0; c < 4; c++) C[a][b][c] = 0.f;
}

// ---------------- edge kernel: CSR-order GEMM + inline completion agg -------
__global__ void __launch_bounds__(256, 2)
k_edge(const float* __restrict__ gh, const float* __restrict__ nf,
       const float* __restrict__ ba1, const float* __restrict__ Wa2,
       const float* __restrict__ ba2, float* __restrict__ out) {
    extern __shared__ char smem[];
    int* seid = reinterpret_cast<int*>(smem + 69632);
    int* ssrc = seid + 128;
    int* sdst = ssrc + 128;
    int* q = sdst + 128;
    __shared__ int qn;
    int m0 = blockIdx.x * TILE;
    int tid = threadIdx.x;
    int lane = tid & 31;
    int wid = tid >> 5;
    int wm = wid >> 1, wn = wid & 1, g = lane >> 2, qd = lane & 3;

    if (blockIdx.x == 0 && tid == 0) g_cursor = 0;  // restore for next replay
    if (tid == 0) qn = 0;
    if (tid < TILE) {
        uint4 rec = g_pk[m0 + tid];
        seid[tid] = (int)rec.x;
        ssrc[tid] = (int)rec.y;
        sdst[tid] = (int)rec.z;
    }
    __syncthreads();

    load_B_async(g_W[2], smem);
    load_A_gather(gh, seid, smem);
    cp_async_wait_all();
    __syncthreads();

    float C[2][8][4];
    zero_C(C);
    mainloop(smem, C);

    float2 bfrag[8], wfrag[8];
#pragma unroll
    for (int nt = 0; nt < 8; nt++) {
        int col = wn * 64 + nt * 8 + qd * 2;
        bfrag[nt] = *reinterpret_cast<const float2*>(ba1 + col);
        wfrag[nt] = *reinterpret_cast<const float2*>(Wa2 + col);
    }

    __syncthreads();  // LDSM reads done; A region reusable for reduction
    float* sred = reinterpret_cast<float*>(smem);

#pragma unroll
    for (int mt = 0; mt < 2; mt++)
#pragma unroll
        for (int hh = 0; hh < 2; hh++) {
            int row = wm * 32 + mt * 16 + hh * 8 + g;
            int es = ssrc[row], ed = sdst[row];
            const __half* Pr = g_P + (size_t)es * FD + wn * 64 + qd * 2;
            const __half* Qr = g_Q + (size_t)ed * FD + wn * 64 + qd * 2;
            float acc = 0.f;
#pragma unroll
            for (int nt = 0; nt < 8; nt++) {
                float2 pf = h2f2(*reinterpret_cast<const uint32_t*>(Pr + nt * 8));
                float2 qf = h2f2(*reinterpret_cast<const uint32_t*>(Qr + nt * 8));
                float c0 = C[mt][nt][hh * 2 + 0];
                float c1 = C[mt][nt][hh * 2 + 1];
                acc += fmaxf(c0 + pf.x + qf.x + bfrag[nt].x, 0.f) * wfrag[nt].x;
                acc += fmaxf(c1 + pf.y + qf.y + bfrag[nt].y, 0.f) * wfrag[nt].y;
            }
            acc += __shfl_xor_sync(0xffffffffu, acc, 1);
            acc += __shfl_xor_sync(0xffffffffu, acc, 2);
            if (qd == 0) sred[row * 2 + wn] = acc;
        }
    __syncthreads();

    // write logit into the CSR record (sequential), then announce arrival
    if (tid < TILE) {
        float a = sred[tid * 2] + sred[tid * 2 + 1] + ba2[0];
        reinterpret_cast<uint32_t*>(&g_pk[m0 + tid])[2] = __float_as_uint(a);
        __threadfence();  // record visible before arrival counts
        int nd = sdst[tid];
        int total = g_end[nd] - g_off[nd];
        int old = atomicAdd(&g_arr[nd], 1);
        if (old == total - 1) {  // last arrival anywhere -> this block aggregates
            int s = atomicAdd(&qn, 1);
            q[s] = nd;
        }
    }
    __syncthreads();

    // warp-cooperative aggregation of completed nodes (single-pass softmax)
    int nq = qn;
    const float4* nf4 = reinterpret_cast<const float4*>(nf);
    const float4* gh4 = reinterpret_cast<const float4*>(gh);
    for (int widx = wid; widx < nq; widx += 8) {
        int node = q[widx];
        int beg = g_off[node], end = g_end[node];
        float4 hv0 = make_float4(0.f, 0.f, 0.f, 0.f);
        float4 hv1 = make_float4(0.f, 0.f, 0.f, 0.f);
        float s0 = 0.f, s1 = 0.f;
        int i = beg;
        for (; i + 2 <= end; i += 2) {
            uint4 r0 = __ldcg(&g_pk[i]);
            uint4 r1 = __ldcg(&g_pk[i + 1]);
            float w0 = __expf(__uint_as_float(r0.z));
            float w1 = __expf(__uint_as_float(r1.z));
            s0 += w0;
            s1 += w1;
            float4 g0 = gh4[(size_t)r0.x * 32 + lane];
            float4 h0 = nf4[(size_t)r0.y * 32 + lane];
            float4 g1 = gh4[(size_t)r1.x * 32 + lane];
            float4 h1 = nf4[(size_t)r1.y * 32 + lane];
            hv0.x += w0 * g0.x * h0.x; hv0.y += w0 * g0.y * h0.y;
            hv0.z += w0 * g0.z * h0.z; hv0.w += w0 * g0.w * h0.w;
            hv1.x += w1 * g1.x * h1.x; hv1.y += w1 * g1.y * h1.y;
            hv1.z += w1 * g1.z * h1.z; hv1.w += w1 * g1.w * h1.w;
        }
        if (i < end) {
            uint4 r0 = __ldcg(&g_pk[i]);
            float w0 = __expf(__uint_as_float(r0.z));
            s0 += w0;
            float4 g0 = gh4[(size_t)r0.x * 32 + lane];
            float4 h0 = nf4[(size_t)r0.y * 32 + lane];
            hv0.x += w0 * g0.x * h0.x; hv0.y += w0 * g0.y * h0.y;
            hv0.z += w0 * g0.z * h0.z; hv0.w += w0 * g0.w * h0.w;
        }
        float s = s0 + s1;
        float inv = (s > 0.f) ? 1.f / s : 0.f;
        float ep = (1.f + g_eps[node]) * inv;
        float4 base = nf4[(size_t)node * 32 + lane];
        float4 r;
        r.x = ep * (hv0.x + hv1.x) + base.x;
        r.y = ep * (hv0.y + hv1.y) + base.y;
        r.z = ep * (hv0.z + hv1.z) + base.z;
        r.w = ep * (hv0.w + hv1.w) + base.w;
        reinterpret_cast<float4*>(out)[(size_t)node * 32 + lane] = r;
    }
}

// ---------------- node kernel: one GEMM per block (3x parallelism) ----------
__global__ void __launch_bounds__(256, 2)
k_node(const float* __restrict__ nf, const float* __restrict__ be1, const float* __restrict__ We2,
       const float* __restrict__ be2) {
    extern __shared__ char smem[];
    int tileIdx = blockIdx.x / 3;
    int z = blockIdx.x % 3;
    int m0 = tileIdx * TILE;
    const int wsel[3] = {0, 1, 3};

    load_B_async(g_W[wsel[z]], smem);
    load_A(nf, m0, NN, smem);
    cp_async_wait_all();
    __syncthreads();

    int lane = threadIdx.x & 31;
    int wid = threadIdx.x >> 5;
    int wm = wid >> 1, wn = wid & 1, g = lane >> 2, q = lane & 3;

    float C[2][8][4];
    zero_C(C);
    mainloop(smem, C);

    if (z < 2) {
        __half* dstbuf = (z == 0) ? g_P : g_Q;
#pragma unroll
        for (int mt = 0; mt < 2; mt++)
#pragma unroll
            for (int nt = 0; nt < 8; nt++) {
                int row = m0 + wm * 32 + mt * 16 + g;
                int col = wn * 64 + nt * 8 + q * 2;
                if (row < NN)
                    *reinterpret_cast<uint32_t*>(dstbuf + (size_t)row * FD + col) =
                        pack_h2(C[mt][nt][0], C[mt][nt][1]);
                if (row + 8 < NN)
                    *reinterpret_cast<uint32_t*>(dstbuf + (size_t)(row + 8) * FD + col) =
                        pack_h2(C[mt][nt][2], C[mt][nt][3]);
            }
    } else {
        float2 bfrag[8], wfrag[8];
#pragma unroll
        for (int nt = 0; nt < 8; nt++) {
            int col = wn * 64 + nt * 8 + q * 2;
            bfrag[nt] = *reinterpret_cast<const float2*>(be1 + col);
            wfrag[nt] = *reinterpret_cast<const float2*>(We2 + col);
        }
        __syncthreads();
        float* sred = reinterpret_cast<float*>(smem);
#pragma unroll
        for (int mt = 0; mt < 2; mt++)
#pragma unroll
            for (int hh = 0; hh < 2; hh++) {
                int row = wm * 32 + mt * 16 + hh * 8 + g;
                float acc = 0.f;
#pragma unroll
                for (int nt = 0; nt < 8; nt++) {
                    float c0 = C[mt][nt][hh * 2 + 0];
                    float c1 = C[mt][nt][hh * 2 + 1];
                    acc += fmaxf(c0 + bfrag[nt].x, 0.f) * wfrag[nt].x;
                    acc += fmaxf(c1 + bfrag[nt].y, 0.f) * wfrag[nt].y;
                }
                acc += __shfl_xor_sync(0xffffffffu, acc, 1);
                acc += __shfl_xor_sync(0xffffffffu, acc, 2);
                if (q == 0) sred[row * 2 + wn] = acc;
            }
        __syncthreads();
        if (threadIdx.x < TILE) {
            int node = m0 + threadIdx.x;
            if (node < NN)
                g_eps[node] = sred[threadIdx.x * 2] + sred[threadIdx.x * 2 + 1] + be2[0];
        }
    }
}

// ---------------- launch -----------------------------------------------------
extern "C" void kernel_launch(void* const* d_in, const int* in_sizes, int n_in,
                              void* d_out, int out_size) {
    const float* nf = (const float*)d_in[0];
    const float* gh = (const float*)d_in[1];
    const int* src = (const int*)d_in[2];
    const int* dst = (const int*)d_in[3];
    const float* Wa1 = (const float*)d_in[4];
    const float* ba1 = (const float*)d_in[5];
    const float* Wa2 = (const float*)d_in[6];
    const float* ba2 = (const float*)d_in[7];
    const float* We1 = (const float*)d_in[8];
    const float* be1 = (const float*)d_in[9];
    const float* We2 = (const float*)d_in[10];
    const float* be2 = (const float*)d_in[11];
    float* out = (float*)d_out;

    // lazily created on the (uncaptured) correctness call; reused during capture
    static cudaStream_t s1 = nullptr;
    static cudaEvent_t ev_fork = nullptr, ev_join = nullptr;
    if (!s1) {
        cudaStreamCreateWithFlags(&s1, cudaStreamNonBlocking);
        cudaEventCreateWithFlags(&ev_fork, cudaEventDisableTiming);
        cudaEventCreateWithFlags(&ev_join, cudaEventDisableTiming);
        cudaFuncSetAttribute(k_node, cudaFuncAttributeMaxDynamicSharedMemorySize, SMEM_N);
        cudaFuncSetAttribute(k_edge, cudaFuncAttributeMaxDynamicSharedMemorySize, SMEM_E);
    }

    // fork: CSR chain (hist -> scan -> scatter) on s1, concurrent with wconv -> node
    cudaEventRecord(ev_fork, 0);
    cudaStreamWaitEvent(s1, ev_fork, 0);
    k_hist<<<(NE + 255) / 256, 256, 0, s1>>>(dst);
    k_scan_fast<<<(NN + 255) / 256, 256, 0, s1>>>(nf, out);
    k_scatter<<<(NE + 255) / 256, 256, 0, s1>>>(dst, src);
    cudaEventRecord(ev_join, s1);

    k_wconv<<<(4 * FD * FD + 255) / 256, 256>>>(Wa1, We1);
    k_node<<<NODE_TILES * 3, 256, SMEM_N>>>(nf, be1, We2, be2);

    cudaStreamWaitEvent(0, ev_join, 0);  // join before k_edge (needs CSR records)
    k_edge<<<NE / TILE, 256, SMEM_E>>>(gh, nf, ba1, Wa2, ba2, out);
}

// round 16
// speedup vs baseline: 1.5419x; 1.5419x over previous
#include <cuda_runtime.h>
#include <cuda_fp16.h>
#include <cstdint>
#include <cstddef>

#define FD 128
#define NN 25000
#define NE 400000
#define TILE 128
// smem: A 128x136 fp16 (34816 B) + B 128x136 fp16 (34816 B)
#define SMEM_BYTES (2 * 128 * 136 * 2)
#define NODE_TILES 196 /* ceil(25000/128) */

// ---------------- device scratch (no allocation allowed) --------------------
__device__ __half g_P[NN * FD];
__device__ __half g_Q[NN * FD];
__device__ float g_eps[NN];
__device__ uint4 g_pk[NE];          // CSR-order packed (eid, esrc, a_bits, 0)
__device__ __half g_W[4][FD * FD];  // [Wt,Wm,Wb,We1] stored [n*FD+k]
__device__ int g_deg[NN];           // invariant: zero on entry (restored by k_agg)
__device__ int g_off[NN];
__device__ int g_end[NN];
__device__ int g_cur[NN];
__device__ int g_cursor;            // invariant: zero on entry (restored by k_agg)

// ---------------- helpers ----------------------------------------------------
__device__ __forceinline__ uint32_t smem_u32(const void* p) {
    uint32_t a;
    asm("{ .reg .u64 t; cvta.to.shared.u64 t, %1; cvt.u32.u64 %0, t; }" : "=r"(a) : "l"(p));
    return a;
}
__device__ __forceinline__ void ldsm4(uint32_t r[4], uint32_t addr) {
    asm volatile("ldmatrix.sync.aligned.m8n8.x4.shared.b16 {%0,%1,%2,%3}, [%4];"
                 : "=r"(r[0]), "=r"(r[1]), "=r"(r[2]), "=r"(r[3])
                 : "r"(addr));
}
__device__ __forceinline__ void mma16816(float c[4], const uint32_t a[4], uint32_t b0,
                                         uint32_t b1) {
    asm volatile(
        "mma.sync.aligned.m16n8k16.row.col.f32.f16.f16.f32 "
        "{%0,%1,%2,%3},{%4,%5,%6,%7},{%8,%9},{%0,%1,%2,%3};"
        : "+f"(c[0]), "+f"(c[1]), "+f"(c[2]), "+f"(c[3])
        : "r"(a[0]), "r"(a[1]), "r"(a[2]), "r"(a[3]), "r"(b0), "r"(b1));
}
__device__ __forceinline__ uint32_t pack_h2(float x, float y) {
    __half2 h = __floats2half2_rn(x, y);
    return *reinterpret_cast<uint32_t*>(&h);
}
__device__ __forceinline__ float2 h2f2(uint32_t u) {
    return __half22float2(*reinterpret_cast<__half2*>(&u));
}
__device__ __forceinline__ void cp_async16(uint32_t smem_addr, const void* gptr) {
    asm volatile("cp.async.cg.shared.global [%0], [%1], 16;" ::"r"(smem_addr), "l"(gptr)
                 : "memory");
}
__device__ __forceinline__ void cp_async_wait_all() {
    asm volatile("cp.async.commit_group;\ncp.async.wait_group 0;" ::: "memory");
}

// ---------------- weight convert (stream 0) ---------------------------------
__global__ void k_wconv(const float* __restrict__ Wa1, const float* __restrict__ We1) {
    int tid = blockIdx.x * blockDim.x + threadIdx.x;
    if (tid < 4 * FD * FD) {
        int m = tid >> 14;
        int r = tid & (FD * FD - 1);
        int n = r >> 7;
        int k = r & 127;
        float w = (m < 3) ? Wa1[(m * FD + k) * FD + n] : We1[k * FD + n];
        g_W[m][n * FD + k] = __float2half(w);
    }
}

// ---------------- degree histogram (stream 1) --------------------------------
__global__ void k_hist(const int* __restrict__ dst) {
    int tid = blockIdx.x * blockDim.x + threadIdx.x;
    if (tid < NE) atomicAdd(&g_deg[dst[tid]], 1);
}

// ---------------- GEMM building blocks (256 threads, C tile 128x128) --------
// A-tile rows are streamed once per block: bypass L1 with .cg loads
__device__ __forceinline__ void load_A(const float* __restrict__ src, int row0, int maxrow,
                                       char* smem) {
    int t = threadIdx.x;
#pragma unroll
    for (int it = 0; it < 16; it++) {
        int linear = it * 256 + t;
        int r = linear >> 5;
        int c = (linear & 31) * 4;
        float4 v = make_float4(0.f, 0.f, 0.f, 0.f);
        if (row0 + r < maxrow)
            v = __ldcg(reinterpret_cast<const float4*>(src + (size_t)(row0 + r) * FD + c));
        uint2 pk;
        pk.x = pack_h2(v.x, v.y);
        pk.y = pack_h2(v.z, v.w);
        *reinterpret_cast<uint2*>(smem + r * 272 + c * 2) = pk;
    }
}
// B fill via cp.async.cg: L2 -> smem direct, no L1/register round trip
__device__ __forceinline__ void load_B_async(const __half* __restrict__ w, char* smem) {
    int t = threadIdx.x;
    uint32_t sB = smem_u32(smem) + 34816;
#pragma unroll
    for (int it = 0; it < 8; it++) {
        int chunk = it * 256 + t;       // 2048 x 16B = 32768 B
        int n = chunk >> 4;             // row (128 rows)
        int k16 = chunk & 15;           // 16B unit within row
        cp_async16(sB + n * 272 + k16 * 16, w + n * FD + k16 * 8);
    }
}

// warp grid 4(M) x 2(N); warp tile 32x64; per-thread C[2][8][4]
__device__ __forceinline__ void mainloop(char* smem, float C[2][8][4]) {
    int lane = threadIdx.x & 31;
    int wid = threadIdx.x >> 5;
    int wm = wid >> 1, wn = wid & 1;
    uint32_t sA = smem_u32(smem);
    uint32_t sB = sA + 34816;
    uint32_t aA0 = sA + (wm * 32 + (lane & 15)) * 272 + (lane >> 4) * 16;
    uint32_t aA1 = aA0 + 16 * 272;
    uint32_t aB[4];
#pragma unroll
    for (int p = 0; p < 4; p++)
        aB[p] = sB + (wn * 64 + p * 16 + (lane & 7) + ((lane >> 4) & 1) * 8) * 272 +
                ((lane >> 3) & 1) * 16;
#pragma unroll
    for (int ks = 0; ks < 8; ks++) {
        uint32_t A0[4], A1[4], Bf[4][4];
        ldsm4(A0, aA0 + ks * 32);
        ldsm4(A1, aA1 + ks * 32);
#pragma unroll
        for (int p = 0; p < 4; p++) ldsm4(Bf[p], aB[p] + ks * 32);
#pragma unroll
        for (int p = 0; p < 4; p++) {
            mma16816(C[0][2 * p], A0, Bf[p][0], Bf[p][1]);
            mma16816(C[1][2 * p], A1, Bf[p][0], Bf[p][1]);
            mma16816(C[0][2 * p + 1], A0, Bf[p][2], Bf[p][3]);
            mma16816(C[1][2 * p + 1], A1, Bf[p][2], Bf[p][3]);
        }
    }
}

__device__ __forceinline__ void zero_C(float C[2][8][4]) {
#pragma unroll
    for (int a = 0; a < 2; a++)
#pragma unroll
        for (int b = 0; b < 8; b++)
#pragma unroll
            for (int c = 0; c < 4; c++) C[a][b][c] = 0.f;
}

// ---------------- edge kernel: GEMM + epilogue + fused CSR scatter ----------
__global__ void __launch_bounds__(256, 2)
k_edge(const float* __restrict__ gh, const int* __restrict__ src, const int* __restrict__ dst,
       const float* __restrict__ ba1, const float* __restrict__ Wa2, const float* __restrict__ ba2) {
    extern __shared__ char smem[];
    int m0 = blockIdx.x * TILE;
    int lane = threadIdx.x & 31;
    int wid = threadIdx.x >> 5;
    int wm = wid >> 1, wn = wid & 1, g = lane >> 2, q = lane & 3;

    // reserve CSR slot up-front: atomic latency hides under fill + mainloop
    int my_e = -1, my_p = 0, my_src = 0;
    if (threadIdx.x < TILE) {
        my_e = m0 + threadIdx.x;
        my_src = src[my_e];
        my_p = atomicAdd(&g_cur[dst[my_e]], 1);
    }

    load_B_async(g_W[2], smem);  // async fill runs under the A convert-fill
    load_A(gh, m0, NE, smem);
    cp_async_wait_all();
    __syncthreads();

    float C[2][8][4];
    zero_C(C);
    mainloop(smem, C);

    float2 bfrag[8], wfrag[8];
#pragma unroll
    for (int nt = 0; nt < 8; nt++) {
        int col = wn * 64 + nt * 8 + q * 2;
        bfrag[nt] = *reinterpret_cast<const float2*>(ba1 + col);
        wfrag[nt] = *reinterpret_cast<const float2*>(Wa2 + col);
    }

    __syncthreads();  // LDSM reads done; smem reusable for reduction
    float* sred = reinterpret_cast<float*>(smem);

#pragma unroll
    for (int mt = 0; mt < 2; mt++)
#pragma unroll
        for (int hh = 0; hh < 2; hh++) {
            int row = wm * 32 + mt * 16 + hh * 8 + g;
            int e = m0 + row;
            int es = src[e], ed = dst[e];
            const __half* Pr = g_P + (size_t)es * FD + wn * 64 + q * 2;
            const __half* Qr = g_Q + (size_t)ed * FD + wn * 64 + q * 2;
            float acc = 0.f;
#pragma unroll
            for (int nt = 0; nt < 8; nt++) {
                float2 pf = h2f2(*reinterpret_cast<const uint32_t*>(Pr + nt * 8));
                float2 qf = h2f2(*reinterpret_cast<const uint32_t*>(Qr + nt * 8));
                float c0 = C[mt][nt][hh * 2 + 0];
                float c1 = C[mt][nt][hh * 2 + 1];
                acc += fmaxf(c0 + pf.x + qf.x + bfrag[nt].x, 0.f) * wfrag[nt].x;
                acc += fmaxf(c1 + pf.y + qf.y + bfrag[nt].y, 0.f) * wfrag[nt].y;
            }
            acc += __shfl_xor_sync(0xffffffffu, acc, 1);
            acc += __shfl_xor_sync(0xffffffffu, acc, 2);
            if (q == 0) sred[row * 2 + wn] = acc;
        }
    __syncthreads();

    // fused scatter: slot already reserved; just write the packed record
    if (threadIdx.x < TILE) {
        float a = sred[threadIdx.x * 2] + sred[threadIdx.x * 2 + 1] + ba2[0];
        uint4 rec;
        rec.x = (uint32_t)my_e;
        rec.y = (uint32_t)my_src;
        rec.z = __float_as_uint(a);
        rec.w = 0u;
        g_pk[my_p] = rec;
    }
}

// ---------------- node kernel: one GEMM per block (3x parallelism) ----------
// blockIdx.x = tile*3 + z; z in {0: P, 1: Q, 2: eps}
__global__ void __launch_bounds__(256, 2)
k_node(const float* __restrict__ nf, const float* __restrict__ be1, const float* __restrict__ We2,
       const float* __restrict__ be2) {
    extern __shared__ char smem[];
    int tileIdx = blockIdx.x / 3;
    int z = blockIdx.x % 3;
    int m0 = tileIdx * TILE;
    const int wsel[3] = {0, 1, 3};

    load_B_async(g_W[wsel[z]], smem);
    load_A(nf, m0, NN, smem);
    cp_async_wait_all();
    __syncthreads();

    int lane = threadIdx.x & 31;
    int wid = threadIdx.x >> 5;
    int wm = wid >> 1, wn = wid & 1, g = lane >> 2, q = lane & 3;

    float C[2][8][4];
    zero_C(C);
    mainloop(smem, C);

    if (z < 2) {
        __half* dstbuf = (z == 0) ? g_P : g_Q;
#pragma unroll
        for (int mt = 0; mt < 2; mt++)
#pragma unroll
            for (int nt = 0; nt < 8; nt++) {
                int row = m0 + wm * 32 + mt * 16 + g;
                int col = wn * 64 + nt * 8 + q * 2;
                if (row < NN)
                    *reinterpret_cast<uint32_t*>(dstbuf + (size_t)row * FD + col) =
                        pack_h2(C[mt][nt][0], C[mt][nt][1]);
                if (row + 8 < NN)
                    *reinterpret_cast<uint32_t*>(dstbuf + (size_t)(row + 8) * FD + col) =
                        pack_h2(C[mt][nt][2], C[mt][nt][3]);
            }
    } else {
        // register-space eps epilogue
        float2 bfrag[8], wfrag[8];
#pragma unroll
        for (int nt = 0; nt < 8; nt++) {
            int col = wn * 64 + nt * 8 + q * 2;
            bfrag[nt] = *reinterpret_cast<const float2*>(be1 + col);
            wfrag[nt] = *reinterpret_cast<const float2*>(We2 + col);
        }
        __syncthreads();
        float* sred = reinterpret_cast<float*>(smem);
#pragma unroll
        for (int mt = 0; mt < 2; mt++)
#pragma unroll
            for (int hh = 0; hh < 2; hh++) {
                int row = wm * 32 + mt * 16 + hh * 8 + g;
                float acc = 0.f;
#pragma unroll
                for (int nt = 0; nt < 8; nt++) {
                    float c0 = C[mt][nt][hh * 2 + 0];
                    float c1 = C[mt][nt][hh * 2 + 1];
                    acc += fmaxf(c0 + bfrag[nt].x, 0.f) * wfrag[nt].x;
                    acc += fmaxf(c1 + bfrag[nt].y, 0.f) * wfrag[nt].y;
                }
                acc += __shfl_xor_sync(0xffffffffu, acc, 1);
                acc += __shfl_xor_sync(0xffffffffu, acc, 2);
                if (q == 0) sred[row * 2 + wn] = acc;
            }
        __syncthreads();
        if (threadIdx.x < TILE) {
            int node = m0 + threadIdx.x;
            if (node < NN)
                g_eps[node] = sred[threadIdx.x * 2] + sred[threadIdx.x * 2 + 1] + be2[0];
        }
    }
}

// ---------------- parallel range assignment (order-free CSR) ----------------
__global__ void k_scan_fast() {
    __shared__ int wsum[8];
    __shared__ int sbase;
    int n = blockIdx.x * 256 + threadIdx.x;
    int lane = threadIdx.x & 31, w = threadIdx.x >> 5;
    int v = (n < NN) ? g_deg[n] : 0;
    int x = v;
#pragma unroll
    for (int d = 1; d < 32; d <<= 1) {
        int t = __shfl_up_sync(0xffffffffu, x, d);
        if (lane >= d) x += t;
    }
    if (lane == 31) wsum[w] = x;
    __syncthreads();
    if (threadIdx.x == 0) {
        int run = 0;
#pragma unroll
        for (int i = 0; i < 8; i++) {
            int t = wsum[i];
            wsum[i] = run;
            run += t;
        }
        sbase = atomicAdd(&g_cursor, run);
    }
    __syncthreads();
    int off = sbase + wsum[w] + x - v;
    if (n < NN) {
        g_off[n] = off;
        g_cur[n] = off;
        g_end[n] = off + v;
    }
}

// ---------------- single-pass softmax aggregation: warp per node ------------
// alpha_e = exp(a_e)/sum(exp(a)); |a| is O(5) by construction, so exp is safe
// in fp32 without max subtraction. One pass: unnormalized sums + denominator.
__global__ void k_agg(const float* __restrict__ nf, const float* __restrict__ gh,
                      float* __restrict__ out) {
    // restore launch invariants for the next replay
    int z = blockIdx.x * blockDim.x + threadIdx.x;
    if (z < NN) g_deg[z] = 0;
    if (z == 0) g_cursor = 0;

    int node = z >> 5;
    int lane = threadIdx.x & 31;
    if (node >= NN) return;
    int beg = g_off[node], end = g_end[node];

    const float4* nf4 = reinterpret_cast<const float4*>(nf);
    const float4* gh4 = reinterpret_cast<const float4*>(gh);
    // hoist per-node loads: overlap their latency with the edge loop
    float eps_n = g_eps[node];
    float4 base = nf4[(size_t)node * 32 + lane];

    float4 hv0 = make_float4(0.f, 0.f, 0.f, 0.f);
    float4 hv1 = make_float4(0.f, 0.f, 0.f, 0.f);
    float4 hv2 = make_float4(0.f, 0.f, 0.f, 0.f);
    float4 hv3 = make_float4(0.f, 0.f, 0.f, 0.f);
    float s0 = 0.f, s1 = 0.f, s2 = 0.f, s3 = 0.f;
    int i = beg;
    for (; i + 4 <= end; i += 4) {
        uint4 r0 = g_pk[i], r1 = g_pk[i + 1], r2 = g_pk[i + 2], r3 = g_pk[i + 3];
        // issue all 8 row loads before any math (deep MLP)
        float4 g0 = gh4[(size_t)r0.x * 32 + lane];
        float4 h0 = nf4[(size_t)r0.y * 32 + lane];
        float4 g1 = gh4[(size_t)r1.x * 32 + lane];
        float4 h1 = nf4[(size_t)r1.y * 32 + lane];
        float4 g2 = gh4[(size_t)r2.x * 32 + lane];
        float4 h2 = nf4[(size_t)r2.y * 32 + lane];
        float4 g3 = gh4[(size_t)r3.x * 32 + lane];
        float4 h3 = nf4[(size_t)r3.y * 32 + lane];
        float w0 = __expf(__uint_as_float(r0.z));
        float w1 = __expf(__uint_as_float(r1.z));
        float w2 = __expf(__uint_as_float(r2.z));
        float w3 = __expf(__uint_as_float(r3.z));
        s0 += w0; s1 += w1; s2 += w2; s3 += w3;
        hv0.x += w0 * g0.x * h0.x; hv0.y += w0 * g0.y * h0.y;
        hv0.z += w0 * g0.z * h0.z; hv0.w += w0 * g0.w * h0.w;
        hv1.x += w1 * g1.x * h1.x; hv1.y += w1 * g1.y * h1.y;
        hv1.z += w1 * g1.z * h1.z; hv1.w += w1 * g1.w * h1.w;
        hv2.x += w2 * g2.x * h2.x; hv2.y += w2 * g2.y * h2.y;
        hv2.z += w2 * g2.z * h2.z; hv2.w += w2 * g2.w * h2.w;
        hv3.x += w3 * g3.x * h3.x; hv3.y += w3 * g3.y * h3.y;
        hv3.z += w3 * g3.z * h3.z; hv3.w += w3 * g3.w * h3.w;
    }
    for (; i < end; i++) {
        uint4 r0 = g_pk[i];
        float4 g0 = gh4[(size_t)r0.x * 32 + lane];
        float4 h0 = nf4[(size_t)r0.y * 32 + lane];
        float w0 = __expf(__uint_as_float(r0.z));
        s0 += w0;
        hv0.x += w0 * g0.x * h0.x; hv0.y += w0 * g0.y * h0.y;
        hv0.z += w0 * g0.z * h0.z; hv0.w += w0 * g0.w * h0.w;
    }
    float s = (s0 + s1) + (s2 + s3);  // identical in all lanes (broadcast loads)
    float inv = (s > 0.f) ? 1.f / s : 0.f;
    float ep = (1.f + eps_n) * inv;
    float4 r;
    r.x = ep * (hv0.x + hv1.x + hv2.x + hv3.x) + base.x;
    r.y = ep * (hv0.y + hv1.y + hv2.y + hv3.y) + base.y;
    r.z = ep * (hv0.z + hv1.z + hv2.z + hv3.z) + base.z;
    r.w = ep * (hv0.w + hv1.w + hv2.w + hv3.w) + base.w;
    reinterpret_cast<float4*>(out)[(size_t)node * 32 + lane] = r;
}

// ---------------- launch -----------------------------------------------------
extern "C" void kernel_launch(void* const* d_in, const int* in_sizes, int n_in,
                              void* d_out, int out_size) {
    const float* nf = (const float*)d_in[0];
    const float* gh = (const float*)d_in[1];
    const int* src = (const int*)d_in[2];
    const int* dst = (const int*)d_in[3];
    const float* Wa1 = (const float*)d_in[4];
    const float* ba1 = (const float*)d_in[5];
    const float* Wa2 = (const float*)d_in[6];
    const float* ba2 = (const float*)d_in[7];
    const float* We1 = (const float*)d_in[8];
    const float* be1 = (const float*)d_in[9];
    const float* We2 = (const float*)d_in[10];
    const float* be2 = (const float*)d_in[11];
    float* out = (float*)d_out;

    // lazily created on the (uncaptured) correctness call; reused during capture
    static cudaStream_t s1 = nullptr;
    static cudaEvent_t ev_fork = nullptr, ev_join = nullptr;
    if (!s1) {
        cudaStreamCreateWithFlags(&s1, cudaStreamNonBlocking);
        cudaEventCreateWithFlags(&ev_fork, cudaEventDisableTiming);
        cudaEventCreateWithFlags(&ev_join, cudaEventDisableTiming);
        cudaFuncSetAttribute(k_node, cudaFuncAttributeMaxDynamicSharedMemorySize, SMEM_BYTES);
        cudaFuncSetAttribute(k_edge, cudaFuncAttributeMaxDynamicSharedMemorySize, SMEM_BYTES);
    }

    // fork: CSR chain (hist -> scan) on s1, concurrent with wconv -> node on s0
    cudaEventRecord(ev_fork, 0);
    cudaStreamWaitEvent(s1, ev_fork, 0);
    k_hist<<<(NE + 255) / 256, 256, 0, s1>>>(dst);
    k_scan_fast<<<(NN + 255) / 256, 256, 0, s1>>>();
    cudaEventRecord(ev_join, s1);

    k_wconv<<<(4 * FD * FD + 255) / 256, 256>>>(Wa1, We1);
    k_node<<<NODE_TILES * 3, 256, SMEM_BYTES>>>(nf, be1, We2, be2);

    cudaStreamWaitEvent(0, ev_join, 0);  // join before k_edge (needs g_cur)
    k_edge<<<NE / TILE, 256, SMEM_BYTES>>>(gh, src, dst, ba1, Wa2, ba2);
    k_agg<<<(NN * 32 + 255) / 256, 256>>>(nf, gh, out);
}